// round 13
// baseline (speedup 1.0000x reference)
#include <cuda_runtime.h>
#include <cuda_bf16.h>
#include <cstdint>

#define N_NODES 50000
#define K_EIG   512
#define F_DIM   128

// ---------------- device scratch (static; no runtime allocation) ----------
__device__ float          g_spec[K_EIG * F_DIM];             // fp32 spec [k][f]
__device__ __nv_bfloat16  g_wt_hi[F_DIM * K_EIG];            // W^T hi [f][k]
__device__ __nv_bfloat16  g_wt_lo[F_DIM * K_EIG];            // W^T lo [f][k]

// ---------------- helpers --------------------------------------------------
static __device__ __forceinline__ uint32_t smem_u32(const void* p) {
    uint32_t a;
    asm("{ .reg .u64 t; cvta.to.shared.u64 t, %1; cvt.u32.u64 %0, t; }" : "=r"(a) : "l"(p));
    return a;
}

#define LDSM_X4(r0, r1, r2, r3, addr) \
    asm volatile("ldmatrix.sync.aligned.m8n8.x4.shared.b16 {%0,%1,%2,%3}, [%4];" \
        : "=r"(r0), "=r"(r1), "=r"(r2), "=r"(r3) : "r"(addr))

#define LDSM_X4_T(r0, r1, r2, r3, addr) \
    asm volatile("ldmatrix.sync.aligned.m8n8.x4.trans.shared.b16 {%0,%1,%2,%3}, [%4];" \
        : "=r"(r0), "=r"(r1), "=r"(r2), "=r"(r3) : "r"(addr))

#define MMA_BF16(c0, c1, c2, c3, a0, a1, a2, a3, b0, b1) \
    asm volatile("mma.sync.aligned.m16n8k16.row.col.f32.bf16.bf16.f32 " \
        "{%0,%1,%2,%3}, {%4,%5,%6,%7}, {%8,%9}, {%0,%1,%2,%3};" \
        : "+f"(c0), "+f"(c1), "+f"(c2), "+f"(c3) \
        : "r"(a0), "r"(a1), "r"(a2), "r"(a3), "r"(b0), "r"(b1))

static __device__ __forceinline__ void cp16(uint32_t dst, const void* src, int sz) {
    asm volatile("cp.async.cg.shared.global [%0], [%1], 16, %2;"
                 :: "r"(dst), "l"(src), "r"(sz));
}
#define CP_COMMIT() asm volatile("cp.async.commit_group;" ::: "memory")
#define CP_WAIT1()  asm volatile("cp.async.wait_group 1;"  ::: "memory")
#define CP_WAIT0()  asm volatile("cp.async.wait_group 0;"  ::: "memory")

static __device__ __forceinline__ uint32_t pack_bf2(__nv_bfloat16 a, __nv_bfloat16 b) {
    __nv_bfloat162 t; t.x = a; t.y = b;
    return *reinterpret_cast<uint32_t*>(&t);
}
static __device__ __forceinline__ void split_bf16(float f, __nv_bfloat16& h, __nv_bfloat16& l) {
    h = __float2bfloat16(f);
    l = __float2bfloat16(f - __bfloat162float(h));
}
// split 8 floats (2 float4) -> hi uint4 + lo uint4
static __device__ __forceinline__ void split8(float4 v0, float4 v1, uint4& hi, uint4& lo) {
    __nv_bfloat16 h[8], l[8];
    split_bf16(v0.x, h[0], l[0]); split_bf16(v0.y, h[1], l[1]);
    split_bf16(v0.z, h[2], l[2]); split_bf16(v0.w, h[3], l[3]);
    split_bf16(v1.x, h[4], l[4]); split_bf16(v1.y, h[5], l[5]);
    split_bf16(v1.z, h[6], l[6]); split_bf16(v1.w, h[7], l[7]);
    hi = make_uint4(pack_bf2(h[0], h[1]), pack_bf2(h[2], h[3]),
                    pack_bf2(h[4], h[5]), pack_bf2(h[6], h[7]));
    lo = make_uint4(pack_bf2(l[0], l[1]), pack_bf2(l[2], l[3]),
                    pack_bf2(l[4], l[5]), pack_bf2(l[6], l[7]));
}

// ---------------- geometry -------------------------------------------------
// phase1: chunk = 32 nodes. fp32 stages (U,X each 32x128 fp32 = 16 KB), ring 2.
// bf16 block: 4 tiles [32 rows][128 cols] bf16 @ stride 272, single-buffered.
#define S1     272
#define T1     (32 * S1)          // 8704
#define F1     16384              // one fp32 operand stage
#define FS1    (2 * F1)           // 32768 per ring slot (U + X)
#define OFFB1  (2 * FS1)          // 65536: bf16 block [Uhi][Ulo][Xhi][Xlo]
#define SMEM1  (OFFB1 + 4 * T1)   // 100352
#define P1_ITERS  22
#define P1_CHUNK  (P1_ITERS * 32) // 704
#define P1_CHUNKS 72              // 4 x 72 = 288 CTAs

// phase2: CTA tile 128 nodes x 64 f, chunk 32 k. Grid 391 x 2 = 782 CTAs.
// A fp32 stage 128x32 fp32 = 16 KB ring 2; A bf16 hi/lo 8 KB each (single);
// B (Wt hi+lo for 64 f) 8 KB/stage ring 3. Total 72 KB -> 3 CTAs/SM.
// bf16 tiles packed 64B rows + XOR swizzle (16B-aligned, conflict-free).
#define P2_TA   (128 * 64)        // 8192 per A bf16 tile
#define P2_TB   (64 * 64)         // 4096 per B bf16 tile
#define P2_BSTG (2 * P2_TB)       // 8192 per B stage (hi+lo)
#define P2_OFFB (2 * 16384)       // 32768: B ring (3 x 8192)
#define P2_OFFA (P2_OFFB + 3 * P2_BSTG)  // 57344: A bf16 [hi][lo]
#define SMEM2   (P2_OFFA + 2 * P2_TA)    // 73728
#define NIT2    (K_EIG / 32)      // 16

static __device__ __forceinline__ uint32_t sw2(uint32_t row, uint32_t seg) {
    return row * 64 + ((seg ^ ((row >> 1) & 3)) << 4);
}

// ---------------------------------------------------------------------------
// Kernel 0: zero spec scratch (graph replays re-zero every call)
// ---------------------------------------------------------------------------
__global__ void zero_spec_kernel() {
    int idx = blockIdx.x * blockDim.x + threadIdx.x;
    reinterpret_cast<float4*>(g_spec)[idx] = make_float4(0.f, 0.f, 0.f, 0.f);
}

// ---------------------------------------------------------------------------
// Phase 1: spec[k,f] += sum_n U[n,k]*x[n,f]   (unchanged from R11)
// ---------------------------------------------------------------------------
static __device__ __forceinline__ void p1_issue(uint32_t sb, int slot, int tid,
                                                const float* U, const float* X,
                                                int k0, int nodebase) {
#pragma unroll
    for (int t = 0; t < 8; t++) {
        const int seg = tid + t * 256;        // 0..2047
        const int tile = seg >> 10;           // 0:U 1:X
        const int s = seg & 1023;
        const int row = s >> 5, sc = s & 31;  // 32 rows x 32 segs of 16B
        const uint32_t dst = sb + slot * FS1 + tile * F1 + (uint32_t)row * 512 + sc * 16;
        const int node = nodebase + row;
        const float* src = tile ? (X + (size_t)node * F_DIM + sc * 4)
                                : (U + (size_t)node * K_EIG + k0 + sc * 4);
        int sz = 16;
        if (node >= N_NODES) { sz = 0; src = (const float*)g_spec; }
        cp16(dst, src, sz);
    }
    CP_COMMIT();
}

static __device__ __forceinline__ void p1_cvt(char* smem, int slot, int tid) {
#pragma unroll
    for (int t = 0; t < 4; t++) {
        const int task = tid + t * 256;       // 0..1023
        const int tile = task >> 9;           // 0:U->A 1:X->B
        const int s = task & 511;
        const int row = s >> 4, seg8 = s & 15;
        const float4* p = reinterpret_cast<const float4*>(
            smem + slot * FS1 + tile * F1 + (uint32_t)row * 512 + seg8 * 32);
        uint4 hi, lo;
        split8(p[0], p[1], hi, lo);
        const uint32_t off = (uint32_t)row * S1 + seg8 * 16;
        char* base = smem + OFFB1 + (tile * 2) * T1;
        *reinterpret_cast<uint4*>(base + off) = hi;
        *reinterpret_cast<uint4*>(base + T1 + off) = lo;
    }
}

static __device__ __forceinline__ void p1_mma(uint32_t base, int wm, int wf,
                                              int lane, float c[2][8][4]) {
#pragma unroll
    for (int ks = 0; ks < 2; ks++) {          // contraction 32 nodes = 2 x kk16
        uint32_t ahi[2][4], alo[2][4];
#pragma unroll
        for (int mi = 0; mi < 2; mi++) {
            const uint32_t row = ks * 16 + (lane & 7) + ((lane >> 4) & 1) * 8;     // node
            const uint32_t col = (wm * 32 + mi * 16 + ((lane >> 3) & 1) * 8) * 2;  // k bytes
            const uint32_t off = row * S1 + col;
            LDSM_X4_T(ahi[mi][0], ahi[mi][1], ahi[mi][2], ahi[mi][3], base + 0 * T1 + off);
            LDSM_X4_T(alo[mi][0], alo[mi][1], alo[mi][2], alo[mi][3], base + 1 * T1 + off);
        }
#pragma unroll
        for (int gp = 0; gp < 4; gp++) {
            const uint32_t row = ks * 16 + (lane & 7) + ((lane >> 3) & 1) * 8;     // node
            const uint32_t col = (wf * 64 + gp * 16 + ((lane >> 4) & 1) * 8) * 2;  // f bytes
            const uint32_t off = row * S1 + col;
            uint32_t bh[4], bl[4];
            LDSM_X4_T(bh[0], bh[1], bh[2], bh[3], base + 2 * T1 + off);
            LDSM_X4_T(bl[0], bl[1], bl[2], bl[3], base + 3 * T1 + off);
#pragma unroll
            for (int mi = 0; mi < 2; mi++) {
#pragma unroll
                for (int gg = 0; gg < 2; gg++) {
                    float* cc = c[mi][gp * 2 + gg];
                    MMA_BF16(cc[0], cc[1], cc[2], cc[3],
                             ahi[mi][0], ahi[mi][1], ahi[mi][2], ahi[mi][3],
                             bh[gg * 2], bh[gg * 2 + 1]);
                    MMA_BF16(cc[0], cc[1], cc[2], cc[3],
                             ahi[mi][0], ahi[mi][1], ahi[mi][2], ahi[mi][3],
                             bl[gg * 2], bl[gg * 2 + 1]);
                    MMA_BF16(cc[0], cc[1], cc[2], cc[3],
                             alo[mi][0], alo[mi][1], alo[mi][2], alo[mi][3],
                             bh[gg * 2], bh[gg * 2 + 1]);
                }
            }
        }
    }
}

__global__ __launch_bounds__(256, 2)
void phase1_mma(const float* __restrict__ U, const float* __restrict__ X) {
    extern __shared__ char smem[];
    const uint32_t sb = smem_u32(smem);
    const int tid = threadIdx.x, wid = tid >> 5, lane = tid & 31;
    const int wm = wid >> 1, wf = wid & 1;

    const int k0    = blockIdx.x * 128;
    const int nbase = blockIdx.y * P1_CHUNK;

    float c[2][8][4];
#pragma unroll
    for (int mi = 0; mi < 2; mi++)
#pragma unroll
        for (int g = 0; g < 8; g++)
#pragma unroll
            for (int r = 0; r < 4; r++) c[mi][g][r] = 0.f;

    p1_issue(sb, 0, tid, U, X, k0, nbase);
    p1_issue(sb, 1, tid, U, X, k0, nbase + 32);
    for (int it = 0; it < P1_ITERS; it++) {
        if (it == P1_ITERS - 1) { CP_WAIT0(); } else { CP_WAIT1(); }
        __syncthreads();                      // fp32 chunk it visible; mma(it-1) done
        p1_cvt(smem, it & 1, tid);
        __syncthreads();                      // bf16 tiles visible; fp32 slot reusable
        if (it + 2 < P1_ITERS)
            p1_issue(sb, it & 1, tid, U, X, k0, nbase + (it + 2) * 32);
        p1_mma(sb + OFFB1, wm, wf, lane, c);
    }

    // reduce into g_spec
#pragma unroll
    for (int mi = 0; mi < 2; mi++) {
        const int k = k0 + wm * 32 + mi * 16 + (lane >> 2);
#pragma unroll
        for (int g = 0; g < 8; g++) {
            const int f = wf * 64 + g * 8 + (lane & 3) * 2;
            atomicAdd(&g_spec[k * F_DIM + f],           c[mi][g][0]);
            atomicAdd(&g_spec[k * F_DIM + f + 1],       c[mi][g][1]);
            atomicAdd(&g_spec[(k + 8) * F_DIM + f],     c[mi][g][2]);
            atomicAdd(&g_spec[(k + 8) * F_DIM + f + 1], c[mi][g][3]);
        }
    }
}

// ---------------------------------------------------------------------------
// Kernel 1.5: Wt[f][k] = split_bf16( g[k] * spec[k][f] )
// ---------------------------------------------------------------------------
__global__ void transpose_scale_kernel(const float* __restrict__ g) {
    __shared__ float tile[32][33];
    const int k0 = blockIdx.x * 32, f0 = blockIdx.y * 32;
    const int tx = threadIdx.x, ty = threadIdx.y;
#pragma unroll
    for (int i = 0; i < 4; i++) {
        const int k = k0 + ty + 8 * i;
        tile[ty + 8 * i][tx] = g_spec[k * F_DIM + f0 + tx] * g[k];
    }
    __syncthreads();
#pragma unroll
    for (int i = 0; i < 4; i++) {
        const int f = f0 + ty + 8 * i;
        const int k = k0 + tx;
        const float v = tile[tx][ty + 8 * i];
        __nv_bfloat16 h = __float2bfloat16(v);
        g_wt_hi[f * K_EIG + k] = h;
        g_wt_lo[f * K_EIG + k] = __float2bfloat16(v - __bfloat162float(h));
    }
}

// ---------------------------------------------------------------------------
// Phase 2: out[n,f] = relu( sum_k U[n,k] * Wt[f,k] )
// CTA tile 128 nodes x 64 f; 8 warps 4x2, warp tile 32x32; 3 CTAs/SM.
// ---------------------------------------------------------------------------
static __device__ __forceinline__ void p2_issue(uint32_t sb, int it, int tid,
                                                const float* U, int n0, int f0, int kc) {
    const int aslot = it & 1, bslot = it % 3;
#pragma unroll
    for (int t = 0; t < 6; t++) {
        const int seg = tid + t * 256;        // 0..1535; first 1024 A fp32, rest B bf16
        uint32_t dst;
        const void* src;
        int sz = 16;
        if (seg < 1024) {
            const int row = seg >> 3, sc = seg & 7;   // 128 rows x 8 segs
            dst = sb + aslot * 16384 + (uint32_t)row * 128 + sc * 16;
            const int node = n0 + row;
            src = U + (size_t)node * K_EIG + kc + sc * 4;
            if (node >= N_NODES) { sz = 0; src = g_spec; }
        } else {
            const int s = seg - 1024;          // 0..511
            const int tile = s >> 8;           // 0:hi 1:lo
            const int r = s & 255;
            const int row = r >> 2, sc = r & 3;  // 64 f rows x 4 segs
            dst = sb + P2_OFFB + bslot * P2_BSTG + tile * P2_TB
                + sw2((uint32_t)row, (uint32_t)sc);
            src = (tile ? g_wt_lo : g_wt_hi) + (size_t)(f0 + row) * K_EIG + kc + sc * 8;
        }
        cp16(dst, src, sz);
    }
    CP_COMMIT();
}

static __device__ __forceinline__ void p2_cvt(char* smem, int slot, int tid) {
#pragma unroll
    for (int t = 0; t < 2; t++) {
        const int task = tid + t * 256;       // 0..511
        const int row = task >> 2, seg8 = task & 3;
        const float4* p = reinterpret_cast<const float4*>(
            smem + slot * 16384 + (uint32_t)row * 128 + seg8 * 32);
        uint4 hi, lo;
        split8(p[0], p[1], hi, lo);
        const uint32_t off = sw2((uint32_t)row, (uint32_t)seg8);
        *reinterpret_cast<uint4*>(smem + P2_OFFA + off) = hi;
        *reinterpret_cast<uint4*>(smem + P2_OFFA + P2_TA + off) = lo;
    }
}

static __device__ __forceinline__ void p2_mma(uint32_t baseA, uint32_t baseB,
                                              int wm, int wf, int lane,
                                              float c[2][4][4]) {
#pragma unroll
    for (int ks = 0; ks < 2; ks++) {          // contraction 32 k = 2 x kk16
        uint32_t ahi[2][4], alo[2][4];
#pragma unroll
        for (int mi = 0; mi < 2; mi++) {
            const uint32_t row = wm * 32 + mi * 16 + (lane & 7) + ((lane >> 3) & 1) * 8;
            const uint32_t off = sw2(row, ks * 2 + (lane >> 4));
            LDSM_X4(ahi[mi][0], ahi[mi][1], ahi[mi][2], ahi[mi][3], baseA + off);
            LDSM_X4(alo[mi][0], alo[mi][1], alo[mi][2], alo[mi][3], baseA + P2_TA + off);
        }
#pragma unroll
        for (int gp = 0; gp < 2; gp++) {
            const uint32_t row = wf * 32 + gp * 16 + (lane & 7) + ((lane >> 4) & 1) * 8;
            const uint32_t off = sw2(row, ks * 2 + ((lane >> 3) & 1));
            uint32_t bh[4], bl[4];
            LDSM_X4(bh[0], bh[1], bh[2], bh[3], baseB + off);
            LDSM_X4(bl[0], bl[1], bl[2], bl[3], baseB + P2_TB + off);
#pragma unroll
            for (int mi = 0; mi < 2; mi++) {
#pragma unroll
                for (int gg = 0; gg < 2; gg++) {
                    float* cc = c[mi][gp * 2 + gg];
                    MMA_BF16(cc[0], cc[1], cc[2], cc[3],
                             ahi[mi][0], ahi[mi][1], ahi[mi][2], ahi[mi][3],
                             bh[gg * 2], bh[gg * 2 + 1]);
                    MMA_BF16(cc[0], cc[1], cc[2], cc[3],
                             ahi[mi][0], ahi[mi][1], ahi[mi][2], ahi[mi][3],
                             bl[gg * 2], bl[gg * 2 + 1]);
                    MMA_BF16(cc[0], cc[1], cc[2], cc[3],
                             alo[mi][0], alo[mi][1], alo[mi][2], alo[mi][3],
                             bh[gg * 2], bh[gg * 2 + 1]);
                }
            }
        }
    }
}

__global__ __launch_bounds__(256, 3)
void phase2_mma(const float* __restrict__ U, float* __restrict__ out) {
    extern __shared__ char smem[];
    const uint32_t sb = smem_u32(smem);
    const int tid = threadIdx.x, wid = tid >> 5, lane = tid & 31;
    const int wm = wid >> 1, wf = wid & 1;

    const int n0 = blockIdx.x * 128;
    const int f0 = blockIdx.y * 64;

    float c[2][4][4];
#pragma unroll
    for (int mi = 0; mi < 2; mi++)
#pragma unroll
        for (int g = 0; g < 4; g++)
#pragma unroll
            for (int r = 0; r < 4; r++) c[mi][g][r] = 0.f;

    p2_issue(sb, 0, tid, U, n0, f0, 0);
    p2_issue(sb, 1, tid, U, n0, f0, 32);
    for (int it = 0; it < NIT2; it++) {
        if (it == NIT2 - 1) { CP_WAIT0(); } else { CP_WAIT1(); }
        __syncthreads();                      // chunk it visible; mma(it-1) done
        p2_cvt(smem, it & 1, tid);
        __syncthreads();                      // A bf16 visible; A fp32 slot reusable
        if (it + 2 < NIT2)
            p2_issue(sb, it + 2, tid, U, n0, f0, (it + 2) * 32);
        p2_mma(sb + P2_OFFA, sb + P2_OFFB + (it % 3) * P2_BSTG, wm, wf, lane, c);
    }

    // relu + store
#pragma unroll
    for (int mi = 0; mi < 2; mi++) {
        const int node = n0 + wm * 32 + mi * 16 + (lane >> 2);
#pragma unroll
        for (int g = 0; g < 4; g++) {
            const int f = f0 + wf * 32 + g * 8 + (lane & 3) * 2;
            if (node < N_NODES) {
                float2 v0;
                v0.x = fmaxf(c[mi][g][0], 0.f);
                v0.y = fmaxf(c[mi][g][1], 0.f);
                *reinterpret_cast<float2*>(out + (size_t)node * F_DIM + f) = v0;
            }
            if (node + 8 < N_NODES) {
                float2 v1;
                v1.x = fmaxf(c[mi][g][2], 0.f);
                v1.y = fmaxf(c[mi][g][3], 0.f);
                *reinterpret_cast<float2*>(out + (size_t)(node + 8) * F_DIM + f) = v1;
            }
        }
    }
}

// ---------------------------------------------------------------------------
// Launch
// ---------------------------------------------------------------------------
extern "C" void kernel_launch(void* const* d_in, const int* in_sizes, int n_in,
                              void* d_out, int out_size) {
    const float* U = (const float*)d_in[0];   // eigenvectors [N, K]
    const float* g = (const float*)d_in[1];   // spectral_filters [K]
    const float* X = (const float*)d_in[2];   // x [N, F]
    float* out = (float*)d_out;               // [N, F]

    cudaFuncSetAttribute(phase1_mma, cudaFuncAttributeMaxDynamicSharedMemorySize, SMEM1);
    cudaFuncSetAttribute(phase2_mma, cudaFuncAttributeMaxDynamicSharedMemorySize, SMEM2);

    zero_spec_kernel<<<64, 256>>>();

    phase1_mma<<<dim3(4, P1_CHUNKS), 256, SMEM1>>>(U, X);

    transpose_scale_kernel<<<dim3(K_EIG / 32, F_DIM / 32), dim3(32, 8)>>>(g);

    phase2_mma<<<dim3((N_NODES + 127) / 128, 2), 256, SMEM2>>>(U, out);
}

// round 14
// speedup vs baseline: 1.0639x; 1.0639x over previous
#include <cuda_runtime.h>
#include <cuda_bf16.h>
#include <cstdint>

#define N_NODES 50000
#define K_EIG   512
#define F_DIM   128

// ---------------- device scratch (static; no runtime allocation) ----------
__device__ float          g_spec[K_EIG * F_DIM];             // fp32 spec [k][f]
__device__ __nv_bfloat16  g_wt_hi[F_DIM * K_EIG];            // W^T hi [f][k]
__device__ __nv_bfloat16  g_wt_lo[F_DIM * K_EIG];            // W^T lo [f][k]

// ---------------- helpers --------------------------------------------------
static __device__ __forceinline__ uint32_t smem_u32(const void* p) {
    uint32_t a;
    asm("{ .reg .u64 t; cvta.to.shared.u64 t, %1; cvt.u32.u64 %0, t; }" : "=r"(a) : "l"(p));
    return a;
}

#define LDSM_X4(r0, r1, r2, r3, addr) \
    asm volatile("ldmatrix.sync.aligned.m8n8.x4.shared.b16 {%0,%1,%2,%3}, [%4];" \
        : "=r"(r0), "=r"(r1), "=r"(r2), "=r"(r3) : "r"(addr))

#define LDSM_X4_T(r0, r1, r2, r3, addr) \
    asm volatile("ldmatrix.sync.aligned.m8n8.x4.trans.shared.b16 {%0,%1,%2,%3}, [%4];" \
        : "=r"(r0), "=r"(r1), "=r"(r2), "=r"(r3) : "r"(addr))

#define MMA_BF16(c0, c1, c2, c3, a0, a1, a2, a3, b0, b1) \
    asm volatile("mma.sync.aligned.m16n8k16.row.col.f32.bf16.bf16.f32 " \
        "{%0,%1,%2,%3}, {%4,%5,%6,%7}, {%8,%9}, {%0,%1,%2,%3};" \
        : "+f"(c0), "+f"(c1), "+f"(c2), "+f"(c3) \
        : "r"(a0), "r"(a1), "r"(a2), "r"(a3), "r"(b0), "r"(b1))

static __device__ __forceinline__ void cp16(uint32_t dst, const void* src, int sz) {
    asm volatile("cp.async.cg.shared.global [%0], [%1], 16, %2;"
                 :: "r"(dst), "l"(src), "r"(sz));
}
#define CP_COMMIT() asm volatile("cp.async.commit_group;" ::: "memory")
#define CP_WAIT1()  asm volatile("cp.async.wait_group 1;"  ::: "memory")
#define CP_WAIT0()  asm volatile("cp.async.wait_group 0;"  ::: "memory")

static __device__ __forceinline__ uint32_t pack_bf2(__nv_bfloat16 a, __nv_bfloat16 b) {
    __nv_bfloat162 t; t.x = a; t.y = b;
    return *reinterpret_cast<uint32_t*>(&t);
}
static __device__ __forceinline__ void split_bf16(float f, __nv_bfloat16& h, __nv_bfloat16& l) {
    h = __float2bfloat16(f);
    l = __float2bfloat16(f - __bfloat162float(h));
}
// split 8 floats (2 float4) -> hi uint4 + lo uint4
static __device__ __forceinline__ void split8(float4 v0, float4 v1, uint4& hi, uint4& lo) {
    __nv_bfloat16 h[8], l[8];
    split_bf16(v0.x, h[0], l[0]); split_bf16(v0.y, h[1], l[1]);
    split_bf16(v0.z, h[2], l[2]); split_bf16(v0.w, h[3], l[3]);
    split_bf16(v1.x, h[4], l[4]); split_bf16(v1.y, h[5], l[5]);
    split_bf16(v1.z, h[6], l[6]); split_bf16(v1.w, h[7], l[7]);
    hi = make_uint4(pack_bf2(h[0], h[1]), pack_bf2(h[2], h[3]),
                    pack_bf2(h[4], h[5]), pack_bf2(h[6], h[7]));
    lo = make_uint4(pack_bf2(l[0], l[1]), pack_bf2(l[2], l[3]),
                    pack_bf2(l[4], l[5]), pack_bf2(l[6], l[7]));
}

// ---------------- geometry -------------------------------------------------
// phase1: chunk = 32 nodes. fp32 stages (U,X each 32x128 fp32 = 16 KB), ring 2.
// bf16 block: 4 tiles [32 rows][128 cols] bf16 @ stride 272, single-buffered.
#define S1     272
#define T1     (32 * S1)          // 8704
#define F1     16384              // one fp32 operand stage
#define FS1    (2 * F1)           // 32768 per ring slot (U + X)
#define OFFB1  (2 * FS1)          // 65536: bf16 block [Uhi][Ulo][Xhi][Xlo]
#define SMEM1  (OFFB1 + 4 * T1)   // 100352
#define P1_ITERS  22
#define P1_CHUNK  (P1_ITERS * 32) // 704
#define P1_CHUNKS 72              // 4 x 72 = 288 CTAs

// phase2: CTA tile 64 nodes x 128 f, chunk 32 k. Grid 782 CTAs, 3 CTAs/SM.
// A fp32 stage 64x32 fp32 = 8 KB ring 2; A bf16 hi/lo 4 KB each (single);
// B (Wt hi+lo, all 128 f) 16 KB/stage ring 3. Total 72 KB.
// bf16 tiles packed 64B rows + XOR swizzle (16B-aligned, conflict-free).
#define P2_FA   8192              // A fp32 stage
#define P2_TA   (64 * 64)         // 4096 per A bf16 tile
#define P2_TB   (128 * 64)        // 8192 per B bf16 tile
#define P2_BSTG (2 * P2_TB)       // 16384 per B stage (hi+lo)
#define P2_OFFB (2 * P2_FA)       // 16384: B ring (3 x 16384)
#define P2_OFFA (P2_OFFB + 3 * P2_BSTG)  // 65536: A bf16 [hi][lo]
#define SMEM2   (P2_OFFA + 2 * P2_TA)    // 73728
#define NIT2    (K_EIG / 32)      // 16
#define P2_GRID ((N_NODES + 63) / 64)    // 782

static __device__ __forceinline__ uint32_t sw2(uint32_t row, uint32_t seg) {
    return row * 64 + ((seg ^ ((row >> 1) & 3)) << 4);
}

// ---------------------------------------------------------------------------
// Kernel 0: zero spec scratch (graph replays re-zero every call)
// ---------------------------------------------------------------------------
__global__ void zero_spec_kernel() {
    int idx = blockIdx.x * blockDim.x + threadIdx.x;
    reinterpret_cast<float4*>(g_spec)[idx] = make_float4(0.f, 0.f, 0.f, 0.f);
}

// ---------------------------------------------------------------------------
// Phase 1: spec[k,f] += sum_n U[n,k]*x[n,f]   (unchanged — best known config)
// ---------------------------------------------------------------------------
static __device__ __forceinline__ void p1_issue(uint32_t sb, int slot, int tid,
                                                const float* U, const float* X,
                                                int k0, int nodebase) {
#pragma unroll
    for (int t = 0; t < 8; t++) {
        const int seg = tid + t * 256;        // 0..2047
        const int tile = seg >> 10;           // 0:U 1:X
        const int s = seg & 1023;
        const int row = s >> 5, sc = s & 31;  // 32 rows x 32 segs of 16B
        const uint32_t dst = sb + slot * FS1 + tile * F1 + (uint32_t)row * 512 + sc * 16;
        const int node = nodebase + row;
        const float* src = tile ? (X + (size_t)node * F_DIM + sc * 4)
                                : (U + (size_t)node * K_EIG + k0 + sc * 4);
        int sz = 16;
        if (node >= N_NODES) { sz = 0; src = (const float*)g_spec; }
        cp16(dst, src, sz);
    }
    CP_COMMIT();
}

static __device__ __forceinline__ void p1_cvt(char* smem, int slot, int tid) {
#pragma unroll
    for (int t = 0; t < 4; t++) {
        const int task = tid + t * 256;       // 0..1023
        const int tile = task >> 9;           // 0:U->A 1:X->B
        const int s = task & 511;
        const int row = s >> 4, seg8 = s & 15;
        const float4* p = reinterpret_cast<const float4*>(
            smem + slot * FS1 + tile * F1 + (uint32_t)row * 512 + seg8 * 32);
        uint4 hi, lo;
        split8(p[0], p[1], hi, lo);
        const uint32_t off = (uint32_t)row * S1 + seg8 * 16;
        char* base = smem + OFFB1 + (tile * 2) * T1;
        *reinterpret_cast<uint4*>(base + off) = hi;
        *reinterpret_cast<uint4*>(base + T1 + off) = lo;
    }
}

static __device__ __forceinline__ void p1_mma(uint32_t base, int wm, int wf,
                                              int lane, float c[2][8][4]) {
#pragma unroll
    for (int ks = 0; ks < 2; ks++) {          // contraction 32 nodes = 2 x kk16
        uint32_t ahi[2][4], alo[2][4];
#pragma unroll
        for (int mi = 0; mi < 2; mi++) {
            const uint32_t row = ks * 16 + (lane & 7) + ((lane >> 4) & 1) * 8;     // node
            const uint32_t col = (wm * 32 + mi * 16 + ((lane >> 3) & 1) * 8) * 2;  // k bytes
            const uint32_t off = row * S1 + col;
            LDSM_X4_T(ahi[mi][0], ahi[mi][1], ahi[mi][2], ahi[mi][3], base + 0 * T1 + off);
            LDSM_X4_T(alo[mi][0], alo[mi][1], alo[mi][2], alo[mi][3], base + 1 * T1 + off);
        }
#pragma unroll
        for (int gp = 0; gp < 4; gp++) {
            const uint32_t row = ks * 16 + (lane & 7) + ((lane >> 3) & 1) * 8;     // node
            const uint32_t col = (wf * 64 + gp * 16 + ((lane >> 4) & 1) * 8) * 2;  // f bytes
            const uint32_t off = row * S1 + col;
            uint32_t bh[4], bl[4];
            LDSM_X4_T(bh[0], bh[1], bh[2], bh[3], base + 2 * T1 + off);
            LDSM_X4_T(bl[0], bl[1], bl[2], bl[3], base + 3 * T1 + off);
#pragma unroll
            for (int mi = 0; mi < 2; mi++) {
#pragma unroll
                for (int gg = 0; gg < 2; gg++) {
                    float* cc = c[mi][gp * 2 + gg];
                    MMA_BF16(cc[0], cc[1], cc[2], cc[3],
                             ahi[mi][0], ahi[mi][1], ahi[mi][2], ahi[mi][3],
                             bh[gg * 2], bh[gg * 2 + 1]);
                    MMA_BF16(cc[0], cc[1], cc[2], cc[3],
                             ahi[mi][0], ahi[mi][1], ahi[mi][2], ahi[mi][3],
                             bl[gg * 2], bl[gg * 2 + 1]);
                    MMA_BF16(cc[0], cc[1], cc[2], cc[3],
                             alo[mi][0], alo[mi][1], alo[mi][2], alo[mi][3],
                             bh[gg * 2], bh[gg * 2 + 1]);
                }
            }
        }
    }
}

__global__ __launch_bounds__(256, 2)
void phase1_mma(const float* __restrict__ U, const float* __restrict__ X) {
    extern __shared__ char smem[];
    const uint32_t sb = smem_u32(smem);
    const int tid = threadIdx.x, wid = tid >> 5, lane = tid & 31;
    const int wm = wid >> 1, wf = wid & 1;

    const int k0    = blockIdx.x * 128;
    const int nbase = blockIdx.y * P1_CHUNK;

    float c[2][8][4];
#pragma unroll
    for (int mi = 0; mi < 2; mi++)
#pragma unroll
        for (int g = 0; g < 8; g++)
#pragma unroll
            for (int r = 0; r < 4; r++) c[mi][g][r] = 0.f;

    p1_issue(sb, 0, tid, U, X, k0, nbase);
    p1_issue(sb, 1, tid, U, X, k0, nbase + 32);
    for (int it = 0; it < P1_ITERS; it++) {
        if (it == P1_ITERS - 1) { CP_WAIT0(); } else { CP_WAIT1(); }
        __syncthreads();                      // fp32 chunk it visible; mma(it-1) done
        p1_cvt(smem, it & 1, tid);
        __syncthreads();                      // bf16 tiles visible; fp32 slot reusable
        if (it + 2 < P1_ITERS)
            p1_issue(sb, it & 1, tid, U, X, k0, nbase + (it + 2) * 32);
        p1_mma(sb + OFFB1, wm, wf, lane, c);
    }

    // reduce into g_spec
#pragma unroll
    for (int mi = 0; mi < 2; mi++) {
        const int k = k0 + wm * 32 + mi * 16 + (lane >> 2);
#pragma unroll
        for (int g = 0; g < 8; g++) {
            const int f = wf * 64 + g * 8 + (lane & 3) * 2;
            atomicAdd(&g_spec[k * F_DIM + f],           c[mi][g][0]);
            atomicAdd(&g_spec[k * F_DIM + f + 1],       c[mi][g][1]);
            atomicAdd(&g_spec[(k + 8) * F_DIM + f],     c[mi][g][2]);
            atomicAdd(&g_spec[(k + 8) * F_DIM + f + 1], c[mi][g][3]);
        }
    }
}

// ---------------------------------------------------------------------------
// Kernel 1.5: Wt[f][k] = split_bf16( g[k] * spec[k][f] )
// ---------------------------------------------------------------------------
__global__ void transpose_scale_kernel(const float* __restrict__ g) {
    __shared__ float tile[32][33];
    const int k0 = blockIdx.x * 32, f0 = blockIdx.y * 32;
    const int tx = threadIdx.x, ty = threadIdx.y;
#pragma unroll
    for (int i = 0; i < 4; i++) {
        const int k = k0 + ty + 8 * i;
        tile[ty + 8 * i][tx] = g_spec[k * F_DIM + f0 + tx] * g[k];
    }
    __syncthreads();
#pragma unroll
    for (int i = 0; i < 4; i++) {
        const int f = f0 + ty + 8 * i;
        const int k = k0 + tx;
        const float v = tile[tx][ty + 8 * i];
        __nv_bfloat16 h = __float2bfloat16(v);
        g_wt_hi[f * K_EIG + k] = h;
        g_wt_lo[f * K_EIG + k] = __float2bfloat16(v - __bfloat162float(h));
    }
}

// ---------------------------------------------------------------------------
// Phase 2: out[n,f] = relu( sum_k U[n,k] * Wt[f,k] )
// CTA tile 64 nodes x 128 f; 8 warps 2x4, warp tile 32x32; 3 CTAs/SM.
// U read once; only small L2-resident Wt re-read across CTAs.
// ---------------------------------------------------------------------------
static __device__ __forceinline__ void p2_issue(uint32_t sb, int it, int tid,
                                                const float* U, int n0, int kc) {
    const int aslot = it & 1, bslot = it % 3;
#pragma unroll
    for (int t = 0; t < 6; t++) {
        const int seg = tid + t * 256;        // 0..1535; first 512 A fp32, rest B bf16
        uint32_t dst;
        const void* src;
        int sz = 16;
        if (seg < 512) {
            const int row = seg >> 3, sc = seg & 7;   // 64 rows x 8 segs
            dst = sb + aslot * P2_FA + (uint32_t)row * 128 + sc * 16;
            const int node = n0 + row;
            src = U + (size_t)node * K_EIG + kc + sc * 4;
            if (node >= N_NODES) { sz = 0; src = g_spec; }
        } else {
            const int s = seg - 512;           // 0..1023
            const int tile = s >> 9;           // 0:hi 1:lo
            const int r = s & 511;
            const int row = r >> 2, sc = r & 3;  // 128 f rows x 4 segs
            dst = sb + P2_OFFB + bslot * P2_BSTG + tile * P2_TB
                + sw2((uint32_t)row, (uint32_t)sc);
            src = (tile ? g_wt_lo : g_wt_hi) + (size_t)row * K_EIG + kc + sc * 8;
        }
        cp16(dst, src, sz);
    }
    CP_COMMIT();
}

static __device__ __forceinline__ void p2_cvt(char* smem, int slot, int tid) {
    // 64 rows x 4 seg8 = 256 tasks -> 1 per thread
    const int row = tid >> 2, seg8 = tid & 3;
    const float4* p = reinterpret_cast<const float4*>(
        smem + slot * P2_FA + (uint32_t)row * 128 + seg8 * 32);
    uint4 hi, lo;
    split8(p[0], p[1], hi, lo);
    const uint32_t off = sw2((uint32_t)row, (uint32_t)seg8);
    *reinterpret_cast<uint4*>(smem + P2_OFFA + off) = hi;
    *reinterpret_cast<uint4*>(smem + P2_OFFA + P2_TA + off) = lo;
}

static __device__ __forceinline__ void p2_mma(uint32_t baseA, uint32_t baseB,
                                              int wm, int wf, int lane,
                                              float c[2][4][4]) {
#pragma unroll
    for (int ks = 0; ks < 2; ks++) {          // contraction 32 k = 2 x kk16
        uint32_t ahi[2][4], alo[2][4];
#pragma unroll
        for (int mi = 0; mi < 2; mi++) {
            const uint32_t row = wm * 32 + mi * 16 + (lane & 7) + ((lane >> 3) & 1) * 8;
            const uint32_t off = sw2(row, ks * 2 + (lane >> 4));
            LDSM_X4(ahi[mi][0], ahi[mi][1], ahi[mi][2], ahi[mi][3], baseA + off);
            LDSM_X4(alo[mi][0], alo[mi][1], alo[mi][2], alo[mi][3], baseA + P2_TA + off);
        }
#pragma unroll
        for (int gp = 0; gp < 2; gp++) {
            const uint32_t row = wf * 32 + gp * 16 + (lane & 7) + ((lane >> 4) & 1) * 8;
            const uint32_t off = sw2(row, ks * 2 + ((lane >> 3) & 1));
            uint32_t bh[4], bl[4];
            LDSM_X4(bh[0], bh[1], bh[2], bh[3], baseB + off);
            LDSM_X4(bl[0], bl[1], bl[2], bl[3], baseB + P2_TB + off);
#pragma unroll
            for (int mi = 0; mi < 2; mi++) {
#pragma unroll
                for (int gg = 0; gg < 2; gg++) {
                    float* cc = c[mi][gp * 2 + gg];
                    MMA_BF16(cc[0], cc[1], cc[2], cc[3],
                             ahi[mi][0], ahi[mi][1], ahi[mi][2], ahi[mi][3],
                             bh[gg * 2], bh[gg * 2 + 1]);
                    MMA_BF16(cc[0], cc[1], cc[2], cc[3],
                             ahi[mi][0], ahi[mi][1], ahi[mi][2], ahi[mi][3],
                             bl[gg * 2], bl[gg * 2 + 1]);
                    MMA_BF16(cc[0], cc[1], cc[2], cc[3],
                             alo[mi][0], alo[mi][1], alo[mi][2], alo[mi][3],
                             bh[gg * 2], bh[gg * 2 + 1]);
                }
            }
        }
    }
}

__global__ __launch_bounds__(256, 3)
void phase2_mma(const float* __restrict__ U, float* __restrict__ out) {
    extern __shared__ char smem[];
    const uint32_t sb = smem_u32(smem);
    const int tid = threadIdx.x, wid = tid >> 5, lane = tid & 31;
    const int wm = wid & 1;        // node half (32 each)
    const int wf = wid >> 1;       // f quarter (32 each)

    const int n0 = blockIdx.x * 64;

    float c[2][4][4];
#pragma unroll
    for (int mi = 0; mi < 2; mi++)
#pragma unroll
        for (int g = 0; g < 4; g++)
#pragma unroll
            for (int r = 0; r < 4; r++) c[mi][g][r] = 0.f;

    p2_issue(sb, 0, tid, U, n0, 0);
    p2_issue(sb, 1, tid, U, n0, 32);
    for (int it = 0; it < NIT2; it++) {
        if (it == NIT2 - 1) { CP_WAIT0(); } else { CP_WAIT1(); }
        __syncthreads();                      // chunk it visible; mma(it-1) done
        p2_cvt(smem, it & 1, tid);
        __syncthreads();                      // A bf16 visible; A fp32 slot reusable
        if (it + 2 < NIT2)
            p2_issue(sb, it + 2, tid, U, n0, (it + 2) * 32);
        p2_mma(sb + P2_OFFA, sb + P2_OFFB + (it % 3) * P2_BSTG, wm, wf, lane, c);
    }

    // relu + store
#pragma unroll
    for (int mi = 0; mi < 2; mi++) {
        const int node = n0 + wm * 32 + mi * 16 + (lane >> 2);
#pragma unroll
        for (int g = 0; g < 4; g++) {
            const int f = wf * 32 + g * 8 + (lane & 3) * 2;
            if (node < N_NODES) {
                float2 v0;
                v0.x = fmaxf(c[mi][g][0], 0.f);
                v0.y = fmaxf(c[mi][g][1], 0.f);
                *reinterpret_cast<float2*>(out + (size_t)node * F_DIM + f) = v0;
            }
            if (node + 8 < N_NODES) {
                float2 v1;
                v1.x = fmaxf(c[mi][g][2], 0.f);
                v1.y = fmaxf(c[mi][g][3], 0.f);
                *reinterpret_cast<float2*>(out + (size_t)(node + 8) * F_DIM + f) = v1;
            }
        }
    }
}

// ---------------------------------------------------------------------------
// Launch
// ---------------------------------------------------------------------------
extern "C" void kernel_launch(void* const* d_in, const int* in_sizes, int n_in,
                              void* d_out, int out_size) {
    const float* U = (const float*)d_in[0];   // eigenvectors [N, K]
    const float* g = (const float*)d_in[1];   // spectral_filters [K]
    const float* X = (const float*)d_in[2];   // x [N, F]
    float* out = (float*)d_out;               // [N, F]

    cudaFuncSetAttribute(phase1_mma, cudaFuncAttributeMaxDynamicSharedMemorySize, SMEM1);
    cudaFuncSetAttribute(phase2_mma, cudaFuncAttributeMaxDynamicSharedMemorySize, SMEM2);

    zero_spec_kernel<<<64, 256>>>();

    phase1_mma<<<dim3(4, P1_CHUNKS), 256, SMEM1>>>(U, X);

    transpose_scale_kernel<<<dim3(K_EIG / 32, F_DIM / 32), dim3(32, 8)>>>(g);

    phase2_mma<<<P2_GRID, 256, SMEM2>>>(U, out);
}